// round 16
// baseline (speedup 1.0000x reference)
#include <cuda_runtime.h>
#include <math.h>

#define NE   32      // experts
#define TK   4       // top_k
#define D    1024    // hidden
#define F    2048    // ffn
#define NTOK 1024    // batch*seq

#define BM 128
#define BN 128
#define BK 16

// ---------------- device scratch (static, allocation-free) ----------------
__device__ float g_probs_sum[NE];          // sum over tokens of softmax probs
__device__ int   g_cnt[NE];                // assignments per expert
__device__ int   g_tok[NE * NTOK];         // token id per assignment
__device__ int   g_slot[NE * NTOK];        // global slot = tok*TK + choice
__device__ float g_wt[NE * NTOK];          // combine weight per assignment
__device__ float g_hbuf[NTOK * TK * F];    // 32 MB intermediate h (gelu(xW1+b1))

// ---------------- zero init ----------------
__global__ void zero_kernel(float* __restrict__ out, int n) {
    int i = blockIdx.x * blockDim.x + threadIdx.x;
    if (i < n) out[i] = 0.0f;
    if (i < NE) { g_probs_sum[i] = 0.0f; g_cnt[i] = 0; }
}

// ---------------- router: one block (32 lanes) per token ----------------
__global__ void router_kernel(const float* __restrict__ x,
                              const float* __restrict__ gw,
                              const float* __restrict__ gb) {
    int tok = blockIdx.x;
    int e   = threadIdx.x;                 // 0..31, one expert per lane
    const float* xr = x + (size_t)tok * D;

    float a0 = 0.f, a1 = 0.f, a2 = 0.f, a3 = 0.f;
    #pragma unroll 8
    for (int h = 0; h < D; h += 4) {
        a0 = fmaf(xr[h + 0], gw[(h + 0) * NE + e], a0);
        a1 = fmaf(xr[h + 1], gw[(h + 1) * NE + e], a1);
        a2 = fmaf(xr[h + 2], gw[(h + 2) * NE + e], a2);
        a3 = fmaf(xr[h + 3], gw[(h + 3) * NE + e], a3);
    }
    float logit = (a0 + a1) + (a2 + a3) + gb[e];

    // full softmax prob (for aux loss)
    float m = logit;
    #pragma unroll
    for (int o = 16; o; o >>= 1) m = fmaxf(m, __shfl_xor_sync(0xffffffffu, m, o));
    float ex = expf(logit - m);
    float s = ex;
    #pragma unroll
    for (int o = 16; o; o >>= 1) s += __shfl_xor_sync(0xffffffffu, s, o);
    atomicAdd(&g_probs_sum[e], ex / s);

    // iterative top-4 argmax (strict >, lowest index on tie = jax top_k)
    float v = logit;
    float tv0, tv1, tv2, tv3;
    int   ti0, ti1, ti2, ti3;
    #pragma unroll
    for (int k = 0; k < TK; k++) {
        float mv = v; int mi = e;
        #pragma unroll
        for (int o = 16; o; o >>= 1) {
            float ov = __shfl_xor_sync(0xffffffffu, mv, o);
            int   oi = __shfl_xor_sync(0xffffffffu, mi, o);
            if (ov > mv || (ov == mv && oi < mi)) { mv = ov; mi = oi; }
        }
        if (k == 0) { tv0 = mv; ti0 = mi; }
        else if (k == 1) { tv1 = mv; ti1 = mi; }
        else if (k == 2) { tv2 = mv; ti2 = mi; }
        else { tv3 = mv; ti3 = mi; }
        if (e == mi) v = -INFINITY;
    }
    // softmax over the 4 selected logits (tv0 is the max)
    float se = expf(tv0 - tv0) + expf(tv1 - tv0) + expf(tv2 - tv0) + expf(tv3 - tv0);

    if (e < TK) {
        float tv = tv0; int ti = ti0;
        if (e == 1) { tv = tv1; ti = ti1; }
        else if (e == 2) { tv = tv2; ti = ti2; }
        else if (e == 3) { tv = tv3; ti = ti3; }
        float w = expf(tv - tv0) / se;
        int pos = atomicAdd(&g_cnt[ti], 1);
        g_tok[ti * NTOK + pos]  = tok;
        g_slot[ti * NTOK + pos] = tok * TK + e;
        g_wt[ti * NTOK + pos]   = w;
    }
}

// ---------------- GEMM1: H[slot] = gelu(x[tok] @ w1[e] + b1[e]) ----------------
__global__ __launch_bounds__(256) void gemm1_kernel(
    const float* __restrict__ x, const float* __restrict__ w1,
    const float* __restrict__ b1) {
    int e    = blockIdx.z;
    int cnt  = g_cnt[e];
    int row0 = blockIdx.y * BM;
    if (row0 >= cnt) return;
    int col0 = blockIdx.x * BN;

    __shared__ float As[BK][BM];
    __shared__ float Bs[BK][BN];
    __shared__ int   rows[BM];

    int tid = threadIdx.x;
    if (tid < BM) {
        int r = row0 + tid;
        rows[tid] = (r < cnt) ? g_tok[e * NTOK + r] : -1;
    }
    __syncthreads();

    int ty = tid >> 4, tx = tid & 15;
    float acc[8][8];
    #pragma unroll
    for (int i = 0; i < 8; i++)
        #pragma unroll
        for (int j = 0; j < 8; j++) acc[i][j] = 0.f;

    // A-load assignment: thread handles row ar, cols [ac, ac+8)
    int ar = tid >> 1;
    int ac = (tid & 1) * 8;
    int atok = rows[ar];
    // B-load assignment: row br, cols [bc, bc+8)
    int br = tid >> 4;
    int bc = (tid & 15) * 8;

    const float* Bbase = w1 + (size_t)e * D * F + col0;

    for (int k0 = 0; k0 < D; k0 += BK) {
        float4 av0 = make_float4(0.f, 0.f, 0.f, 0.f), av1 = av0;
        if (atok >= 0) {
            const float4* ap = (const float4*)(x + (size_t)atok * D + k0 + ac);
            av0 = ap[0]; av1 = ap[1];
        }
        const float4* bp = (const float4*)(Bbase + (size_t)(k0 + br) * F + bc);
        float4 bv0 = bp[0], bv1 = bp[1];

        As[ac + 0][ar] = av0.x; As[ac + 1][ar] = av0.y;
        As[ac + 2][ar] = av0.z; As[ac + 3][ar] = av0.w;
        As[ac + 4][ar] = av1.x; As[ac + 5][ar] = av1.y;
        As[ac + 6][ar] = av1.z; As[ac + 7][ar] = av1.w;
        *(float4*)&Bs[br][bc]     = bv0;
        *(float4*)&Bs[br][bc + 4] = bv1;
        __syncthreads();

        #pragma unroll
        for (int k = 0; k < BK; k++) {
            float4 A0 = *(const float4*)&As[k][ty * 4];
            float4 A1 = *(const float4*)&As[k][ty * 4 + 64];
            float4 B0 = *(const float4*)&Bs[k][tx * 4];
            float4 B1 = *(const float4*)&Bs[k][tx * 4 + 64];
            float axv[8] = {A0.x, A0.y, A0.z, A0.w, A1.x, A1.y, A1.z, A1.w};
            float bxv[8] = {B0.x, B0.y, B0.z, B0.w, B1.x, B1.y, B1.z, B1.w};
            #pragma unroll
            for (int i = 0; i < 8; i++)
                #pragma unroll
                for (int j = 0; j < 8; j++)
                    acc[i][j] = fmaf(axv[i], bxv[j], acc[i][j]);
        }
        __syncthreads();
    }

    // epilogue: bias + exact-erf gelu -> hbuf
    #pragma unroll
    for (int i = 0; i < 8; i++) {
        int rloc = (i < 4) ? (ty * 4 + i) : (64 + ty * 4 + (i - 4));
        int r = row0 + rloc;
        if (r >= cnt) continue;
        int slot = g_slot[e * NTOK + r];
        float* hrow = g_hbuf + (size_t)slot * F + col0;
        #pragma unroll
        for (int j = 0; j < 8; j++) {
            int cloc = (j < 4) ? (tx * 4 + j) : (64 + tx * 4 + (j - 4));
            float val = acc[i][j] + b1[e * F + col0 + cloc];
            hrow[cloc] = 0.5f * val * (1.0f + erff(val * 0.70710678118654752f));
        }
    }
}

// ---------------- GEMM2: out[tok] += ce * (H[slot] @ w2[e] + b2[e]) ----------------
__global__ __launch_bounds__(256) void gemm2_kernel(
    const float* __restrict__ w2, const float* __restrict__ b2,
    float* __restrict__ out) {
    int e    = blockIdx.z;
    int cnt  = g_cnt[e];
    int row0 = blockIdx.y * BM;
    if (row0 >= cnt) return;
    int col0 = blockIdx.x * BN;

    __shared__ float As[BK][BM];
    __shared__ float Bs[BK][BN];
    __shared__ int   slots[BM];
    __shared__ int   toks[BM];
    __shared__ float wts[BM];

    int tid = threadIdx.x;
    if (tid < BM) {
        int r = row0 + tid;
        if (r < cnt) {
            slots[tid] = g_slot[e * NTOK + r];
            toks[tid]  = g_tok[e * NTOK + r];
            wts[tid]   = g_wt[e * NTOK + r];
        } else {
            slots[tid] = -1; toks[tid] = 0; wts[tid] = 0.f;
        }
    }
    __syncthreads();

    int ty = tid >> 4, tx = tid & 15;
    float acc[8][8];
    #pragma unroll
    for (int i = 0; i < 8; i++)
        #pragma unroll
        for (int j = 0; j < 8; j++) acc[i][j] = 0.f;

    int ar = tid >> 1;
    int ac = (tid & 1) * 8;
    int aslot = slots[ar];
    int br = tid >> 4;
    int bc = (tid & 15) * 8;

    const float* Bbase = w2 + (size_t)e * F * D + col0;

    for (int k0 = 0; k0 < F; k0 += BK) {
        float4 av0 = make_float4(0.f, 0.f, 0.f, 0.f), av1 = av0;
        if (aslot >= 0) {
            const float4* ap = (const float4*)(g_hbuf + (size_t)aslot * F + k0 + ac);
            av0 = ap[0]; av1 = ap[1];
        }
        const float4* bp = (const float4*)(Bbase + (size_t)(k0 + br) * D + bc);
        float4 bv0 = bp[0], bv1 = bp[1];

        As[ac + 0][ar] = av0.x; As[ac + 1][ar] = av0.y;
        As[ac + 2][ar] = av0.z; As[ac + 3][ar] = av0.w;
        As[ac + 4][ar] = av1.x; As[ac + 5][ar] = av1.y;
        As[ac + 6][ar] = av1.z; As[ac + 7][ar] = av1.w;
        *(float4*)&Bs[br][bc]     = bv0;
        *(float4*)&Bs[br][bc + 4] = bv1;
        __syncthreads();

        #pragma unroll
        for (int k = 0; k < BK; k++) {
            float4 A0 = *(const float4*)&As[k][ty * 4];
            float4 A1 = *(const float4*)&As[k][ty * 4 + 64];
            float4 B0 = *(const float4*)&Bs[k][tx * 4];
            float4 B1 = *(const float4*)&Bs[k][tx * 4 + 64];
            float axv[8] = {A0.x, A0.y, A0.z, A0.w, A1.x, A1.y, A1.z, A1.w};
            float bxv[8] = {B0.x, B0.y, B0.z, B0.w, B1.x, B1.y, B1.z, B1.w};
            #pragma unroll
            for (int i = 0; i < 8; i++)
                #pragma unroll
                for (int j = 0; j < 8; j++)
                    acc[i][j] = fmaf(axv[i], bxv[j], acc[i][j]);
        }
        __syncthreads();
    }

    #pragma unroll
    for (int i = 0; i < 8; i++) {
        int rloc = (i < 4) ? (ty * 4 + i) : (64 + ty * 4 + (i - 4));
        int r = row0 + rloc;
        if (r >= cnt) continue;
        int tok = toks[rloc];
        float w = wts[rloc];
        float* orow = out + (size_t)tok * D + col0;
        #pragma unroll
        for (int j = 0; j < 8; j++) {
            int cloc = (j < 4) ? (tx * 4 + j) : (64 + tx * 4 + (j - 4));
            float val = (acc[i][j] + b2[e * D + col0 + cloc]) * w;
            atomicAdd(&orow[cloc], val);
        }
    }
}

// ---------------- aux loss scalar ----------------
__global__ void aux_kernel(const float* __restrict__ load_ema,
                           float* __restrict__ out_aux) {
    float base = 0.f;
    for (int e = 0; e < NE; e++) {
        float frac = ((float)g_cnt[e] / (float)NTOK) / (float)TK;
        float pm   = g_probs_sum[e] / (float)NTOK;
        base += frac * pm;
    }
    base *= (float)NE;
    float s = 0.f;
    for (int e = 0; e < NE; e++) s += load_ema[e];
    float ent = 0.f;
    for (int e = 0; e < NE; e++) {
        float lp = load_ema[e] / (s + 1e-8f);
        ent -= lp * logf(lp + 1e-8f);
    }
    float reg = logf((float)NE) - ent;
    out_aux[0] = base + 0.001f * reg;
}

// ---------------- launch ----------------
extern "C" void kernel_launch(void* const* d_in, const int* in_sizes, int n_in,
                              void* d_out, int out_size) {
    const float* x   = (const float*)d_in[0];
    const float* gw  = (const float*)d_in[1];
    const float* gb  = (const float*)d_in[2];
    const float* w1  = (const float*)d_in[3];
    const float* b1  = (const float*)d_in[4];
    const float* w2  = (const float*)d_in[5];
    const float* b2  = (const float*)d_in[6];
    const float* ema = (const float*)d_in[7];
    float* out = (float*)d_out;

    const int nOut = NTOK * D;

    zero_kernel<<<(nOut + 255) / 256, 256>>>(out, nOut);
    router_kernel<<<NTOK, 32>>>(x, gw, gb);
    gemm1_kernel<<<dim3(F / BN, NTOK / BM, NE), 256>>>(x, w1, b1);
    gemm2_kernel<<<dim3(D / BN, NTOK / BM, NE), 256>>>(w2, b2, out);
    if (out_size > nOut) {
        aux_kernel<<<1, 1>>>(ema, out + nOut);
    }
}

// round 17
// speedup vs baseline: 2.3897x; 2.3897x over previous
#include <cuda_runtime.h>
#include <math.h>
#include <stdint.h>

#define NE   32      // experts
#define TK   4       // top_k
#define D    1024    // hidden
#define F    2048    // ffn
#define NTOK 1024    // batch*seq

#define BM 128
#define BN 128
#define BK 16
#define ASTRIDE (BM + 8)   // 136: conflict-free fragment loads
#define BSTRIDE (BN + 8)

// ---------------- device scratch (static, allocation-free) ----------------
__device__ float g_probs_sum[NE];
__device__ int   g_cnt[NE];
__device__ int   g_tok[NE * NTOK];
__device__ int   g_slot[NE * NTOK];
__device__ float g_wt[NE * NTOK];
__device__ float g_hbuf[NTOK * TK * F];    // 32 MB intermediate gelu(xW1+b1)

// ---------------- helpers ----------------
__device__ __forceinline__ uint32_t f2tf32(float f) {
    uint32_t u;
    asm("cvt.rna.tf32.f32 %0, %1;" : "=r"(u) : "f"(f));
    return u;
}

__device__ __forceinline__ void mma_tf32(float c[4],
    uint32_t a0, uint32_t a1, uint32_t a2, uint32_t a3,
    uint32_t b0, uint32_t b1)
{
    asm volatile(
        "mma.sync.aligned.m16n8k8.row.col.f32.tf32.tf32.f32 "
        "{%0,%1,%2,%3}, {%4,%5,%6,%7}, {%8,%9}, {%0,%1,%2,%3};\n"
        : "+f"(c[0]), "+f"(c[1]), "+f"(c[2]), "+f"(c[3])
        : "r"(a0), "r"(a1), "r"(a2), "r"(a3), "r"(b0), "r"(b1));
}

__device__ __forceinline__ void load_a_g(const float* aptr, int k0, int a_c, float av[8]) {
    if (aptr) {
        float4 v0 = *(const float4*)(aptr + k0 + a_c);
        float4 v1 = *(const float4*)(aptr + k0 + a_c + 4);
        av[0]=v0.x; av[1]=v0.y; av[2]=v0.z; av[3]=v0.w;
        av[4]=v1.x; av[5]=v1.y; av[6]=v1.z; av[7]=v1.w;
    } else {
        #pragma unroll
        for (int j = 0; j < 8; j++) av[j] = 0.f;
    }
}

__device__ __forceinline__ void store_a_s(uint32_t (*As)[ASTRIDE], int a_r, int a_c, const float av[8]) {
    #pragma unroll
    for (int j = 0; j < 8; j++) As[a_c + j][a_r] = f2tf32(av[j]);
}

__device__ __forceinline__ void load_b_g(const float* bbase, int ldb, int k0, int b_r, int b_c, float bv[8]) {
    const float4* p = (const float4*)(bbase + (size_t)(k0 + b_r) * ldb + b_c);
    float4 v0 = p[0], v1 = p[1];
    bv[0]=v0.x; bv[1]=v0.y; bv[2]=v0.z; bv[3]=v0.w;
    bv[4]=v1.x; bv[5]=v1.y; bv[6]=v1.z; bv[7]=v1.w;
}

__device__ __forceinline__ void store_b_s(uint32_t (*Bs)[BSTRIDE], int b_r, int b_c, const float bv[8]) {
    #pragma unroll
    for (int j = 0; j < 8; j++) Bs[b_r][b_c + j] = f2tf32(bv[j]);
}

// 2 k-steps of 8 over one BK=16 buffer: 32 mma per warp
__device__ __forceinline__ void compute_block(
    const uint32_t (*As)[ASTRIDE], const uint32_t (*Bs)[BSTRIDE],
    int wm, int wn, int gr, int gc, float acc[4][4][4])
{
    #pragma unroll
    for (int ks = 0; ks < BK; ks += 8) {
        uint32_t af[4][4], bf[4][2];
        #pragma unroll
        for (int mt = 0; mt < 4; mt++) {
            int m = wm + mt * 16 + gr;
            af[mt][0] = As[ks + gc][m];
            af[mt][1] = As[ks + gc][m + 8];
            af[mt][2] = As[ks + gc + 4][m];
            af[mt][3] = As[ks + gc + 4][m + 8];
        }
        #pragma unroll
        for (int nt = 0; nt < 4; nt++) {
            int n = wn + nt * 8 + gr;
            bf[nt][0] = Bs[ks + gc][n];
            bf[nt][1] = Bs[ks + gc + 4][n];
        }
        #pragma unroll
        for (int mt = 0; mt < 4; mt++)
            #pragma unroll
            for (int nt = 0; nt < 4; nt++)
                mma_tf32(acc[mt][nt], af[mt][0], af[mt][1], af[mt][2], af[mt][3],
                         bf[nt][0], bf[nt][1]);
    }
}

// ---------------- zero init ----------------
__global__ void zero_kernel(float* __restrict__ out, int n) {
    int i = blockIdx.x * blockDim.x + threadIdx.x;
    if (i < n) out[i] = 0.0f;
    if (i < NE) { g_probs_sum[i] = 0.0f; g_cnt[i] = 0; }
}

// ---------------- router: one warp per token, 8 tokens/block ----------------
__global__ void router_kernel(const float* __restrict__ x,
                              const float* __restrict__ gw,
                              const float* __restrict__ gb) {
    int tok = blockIdx.x * 8 + (threadIdx.x >> 5);
    int e   = threadIdx.x & 31;
    const float* xr = x + (size_t)tok * D;

    float a0 = 0.f, a1 = 0.f, a2 = 0.f, a3 = 0.f;
    #pragma unroll 8
    for (int h = 0; h < D; h += 4) {
        a0 = fmaf(xr[h + 0], gw[(h + 0) * NE + e], a0);
        a1 = fmaf(xr[h + 1], gw[(h + 1) * NE + e], a1);
        a2 = fmaf(xr[h + 2], gw[(h + 2) * NE + e], a2);
        a3 = fmaf(xr[h + 3], gw[(h + 3) * NE + e], a3);
    }
    float logit = (a0 + a1) + (a2 + a3) + gb[e];

    // full softmax prob (for aux loss)
    float m = logit;
    #pragma unroll
    for (int o = 16; o; o >>= 1) m = fmaxf(m, __shfl_xor_sync(0xffffffffu, m, o));
    float ex = expf(logit - m);
    float s = ex;
    #pragma unroll
    for (int o = 16; o; o >>= 1) s += __shfl_xor_sync(0xffffffffu, s, o);
    atomicAdd(&g_probs_sum[e], ex / s);

    // iterative top-4 argmax (strict >, lowest index on tie = jax top_k)
    float v = logit;
    float tv0, tv1, tv2, tv3;
    int   ti0, ti1, ti2, ti3;
    #pragma unroll
    for (int k = 0; k < TK; k++) {
        float mv = v; int mi = e;
        #pragma unroll
        for (int o = 16; o; o >>= 1) {
            float ov = __shfl_xor_sync(0xffffffffu, mv, o);
            int   oi = __shfl_xor_sync(0xffffffffu, mi, o);
            if (ov > mv || (ov == mv && oi < mi)) { mv = ov; mi = oi; }
        }
        if (k == 0) { tv0 = mv; ti0 = mi; }
        else if (k == 1) { tv1 = mv; ti1 = mi; }
        else if (k == 2) { tv2 = mv; ti2 = mi; }
        else { tv3 = mv; ti3 = mi; }
        if (e == mi) v = -INFINITY;
    }
    float se = expf(tv0 - tv0) + expf(tv1 - tv0) + expf(tv2 - tv0) + expf(tv3 - tv0);

    if (e < TK) {
        float tv = tv0; int ti = ti0;
        if (e == 1) { tv = tv1; ti = ti1; }
        else if (e == 2) { tv = tv2; ti = ti2; }
        else if (e == 3) { tv = tv3; ti = ti3; }
        float w = expf(tv - tv0) / se;
        int pos = atomicAdd(&g_cnt[ti], 1);
        g_tok[ti * NTOK + pos]  = tok;
        g_slot[ti * NTOK + pos] = tok * TK + e;
        g_wt[ti * NTOK + pos]   = w;
    }
}

// ---------------- GEMM1 (tf32 mma): H[slot] = gelu(x[tok] @ w1[e] + b1[e]) ----------------
__global__ __launch_bounds__(256) void gemm1_kernel(
    const float* __restrict__ x, const float* __restrict__ w1,
    const float* __restrict__ b1)
{
    int e    = blockIdx.z;
    int cnt  = g_cnt[e];
    int row0 = blockIdx.y * BM;
    if (row0 >= cnt) return;
    int col0 = blockIdx.x * BN;

    __shared__ uint32_t As[2][BK][ASTRIDE];
    __shared__ uint32_t Bs[2][BK][BSTRIDE];
    __shared__ int rows_s[BM];
    __shared__ int slots_s[BM];

    int tid = threadIdx.x;
    if (tid < BM) {
        int r = row0 + tid;
        rows_s[tid]  = (r < cnt) ? g_tok[e * NTOK + r] : -1;
        slots_s[tid] = (r < cnt) ? g_slot[e * NTOK + r] : -1;
    }
    __syncthreads();

    int a_r = tid >> 1, a_c = (tid & 1) * 8;
    int atok = rows_s[a_r];
    const float* aptr = (atok >= 0) ? (x + (size_t)atok * D) : nullptr;
    int b_r = tid >> 4, b_c = (tid & 15) * 8;
    const float* bbase = w1 + (size_t)e * D * F + col0;

    int warp = tid >> 5, lane = tid & 31;
    int wm = (warp >> 2) * 64, wn = (warp & 3) * 32;
    int gr = lane >> 2, gc = lane & 3;

    float acc[4][4][4];
    #pragma unroll
    for (int i = 0; i < 4; i++)
        #pragma unroll
        for (int j = 0; j < 4; j++)
            #pragma unroll
            for (int k = 0; k < 4; k++) acc[i][j][k] = 0.f;

    float av[8], bv[8];
    load_a_g(aptr, 0, a_c, av);
    load_b_g(bbase, F, 0, b_r, b_c, bv);
    store_a_s(As[0], a_r, a_c, av);
    store_b_s(Bs[0], b_r, b_c, bv);
    __syncthreads();

    const int NKB = D / BK;
    for (int kb = 0; kb < NKB; kb++) {
        int cur = kb & 1;
        if (kb + 1 < NKB) {
            load_a_g(aptr, (kb + 1) * BK, a_c, av);
            load_b_g(bbase, F, (kb + 1) * BK, b_r, b_c, bv);
        }
        compute_block(As[cur], Bs[cur], wm, wn, gr, gc, acc);
        if (kb + 1 < NKB) {
            store_a_s(As[cur ^ 1], a_r, a_c, av);
            store_b_s(Bs[cur ^ 1], b_r, b_c, bv);
            __syncthreads();
        }
    }

    // epilogue: bias + exact-erf gelu -> hbuf
    #pragma unroll
    for (int mt = 0; mt < 4; mt++) {
        #pragma unroll
        for (int half = 0; half < 2; half++) {
            int rl = wm + mt * 16 + gr + half * 8;
            if (row0 + rl < cnt) {
                int slot = slots_s[rl];
                float* hrow = g_hbuf + (size_t)slot * F + col0;
                #pragma unroll
                for (int nt = 0; nt < 4; nt++) {
                    int cl = wn + nt * 8 + gc * 2;
                    float v0 = acc[mt][nt][half * 2 + 0] + b1[e * F + col0 + cl];
                    float v1 = acc[mt][nt][half * 2 + 1] + b1[e * F + col0 + cl + 1];
                    v0 = 0.5f * v0 * (1.0f + erff(v0 * 0.70710678118654752f));
                    v1 = 0.5f * v1 * (1.0f + erff(v1 * 0.70710678118654752f));
                    *(float2*)(hrow + cl) = make_float2(v0, v1);
                }
            }
        }
    }
}

// ---------------- GEMM2 (tf32 mma): out[tok] += ce * (H[slot] @ w2[e] + b2[e]) ----------------
__global__ __launch_bounds__(256) void gemm2_kernel(
    const float* __restrict__ w2, const float* __restrict__ b2,
    float* __restrict__ out)
{
    int e    = blockIdx.z;
    int cnt  = g_cnt[e];
    int row0 = blockIdx.y * BM;
    if (row0 >= cnt) return;
    int col0 = blockIdx.x * BN;

    __shared__ uint32_t As[2][BK][ASTRIDE];
    __shared__ uint32_t Bs[2][BK][BSTRIDE];
    __shared__ int   slots_s[BM];
    __shared__ int   toks_s[BM];
    __shared__ float wts_s[BM];

    int tid = threadIdx.x;
    if (tid < BM) {
        int r = row0 + tid;
        if (r < cnt) {
            slots_s[tid] = g_slot[e * NTOK + r];
            toks_s[tid]  = g_tok[e * NTOK + r];
            wts_s[tid]   = g_wt[e * NTOK + r];
        } else {
            slots_s[tid] = -1; toks_s[tid] = 0; wts_s[tid] = 0.f;
        }
    }
    __syncthreads();

    int a_r = tid >> 1, a_c = (tid & 1) * 8;
    int aslot = slots_s[a_r];
    const float* aptr = (aslot >= 0) ? (g_hbuf + (size_t)aslot * F) : nullptr;
    int b_r = tid >> 4, b_c = (tid & 15) * 8;
    const float* bbase = w2 + (size_t)e * F * D + col0;

    int warp = tid >> 5, lane = tid & 31;
    int wm = (warp >> 2) * 64, wn = (warp & 3) * 32;
    int gr = lane >> 2, gc = lane & 3;

    float acc[4][4][4];
    #pragma unroll
    for (int i = 0; i < 4; i++)
        #pragma unroll
        for (int j = 0; j < 4; j++)
            #pragma unroll
            for (int k = 0; k < 4; k++) acc[i][j][k] = 0.f;

    float av[8], bv[8];
    load_a_g(aptr, 0, a_c, av);
    load_b_g(bbase, D, 0, b_r, b_c, bv);
    store_a_s(As[0], a_r, a_c, av);
    store_b_s(Bs[0], b_r, b_c, bv);
    __syncthreads();

    const int NKB = F / BK;
    for (int kb = 0; kb < NKB; kb++) {
        int cur = kb & 1;
        if (kb + 1 < NKB) {
            load_a_g(aptr, (kb + 1) * BK, a_c, av);
            load_b_g(bbase, D, (kb + 1) * BK, b_r, b_c, bv);
        }
        compute_block(As[cur], Bs[cur], wm, wn, gr, gc, acc);
        if (kb + 1 < NKB) {
            store_a_s(As[cur ^ 1], a_r, a_c, av);
            store_b_s(Bs[cur ^ 1], b_r, b_c, bv);
            __syncthreads();
        }
    }

    // epilogue: bias + combine-weight scale, atomic accumulate into out
    #pragma unroll
    for (int mt = 0; mt < 4; mt++) {
        #pragma unroll
        for (int half = 0; half < 2; half++) {
            int rl = wm + mt * 16 + gr + half * 8;
            if (row0 + rl < cnt) {
                int tok = toks_s[rl];
                float w = wts_s[rl];
                float* orow = out + (size_t)tok * D + col0;
                #pragma unroll
                for (int nt = 0; nt < 4; nt++) {
                    int cl = wn + nt * 8 + gc * 2;
                    float v0 = (acc[mt][nt][half * 2 + 0] + b2[e * D + col0 + cl]) * w;
                    float v1 = (acc[mt][nt][half * 2 + 1] + b2[e * D + col0 + cl + 1]) * w;
                    atomicAdd(&orow[cl],     v0);
                    atomicAdd(&orow[cl + 1], v1);
                }
            }
        }
    }
}

// ---------------- aux loss scalar ----------------
__global__ void aux_kernel(const float* __restrict__ load_ema,
                           float* __restrict__ out_aux) {
    float base = 0.f;
    for (int e = 0; e < NE; e++) {
        float frac = ((float)g_cnt[e] / (float)NTOK) / (float)TK;
        float pm   = g_probs_sum[e] / (float)NTOK;
        base += frac * pm;
    }
    base *= (float)NE;
    float s = 0.f;
    for (int e = 0; e < NE; e++) s += load_ema[e];
    float ent = 0.f;
    for (int e = 0; e < NE; e++) {
        float lp = load_ema[e] / (s + 1e-8f);
        ent -= lp * logf(lp + 1e-8f);
    }
    float reg = logf((float)NE) - ent;
    out_aux[0] = base + 0.001f * reg;
}

// ---------------- launch ----------------
extern "C" void kernel_launch(void* const* d_in, const int* in_sizes, int n_in,
                              void* d_out, int out_size) {
    const float* x   = (const float*)d_in[0];
    const float* gw  = (const float*)d_in[1];
    const float* gb  = (const float*)d_in[2];
    const float* w1  = (const float*)d_in[3];
    const float* b1  = (const float*)d_in[4];
    const float* w2  = (const float*)d_in[5];
    const float* b2  = (const float*)d_in[6];
    const float* ema = (const float*)d_in[7];
    float* out = (float*)d_out;

    const int nOut = NTOK * D;

    zero_kernel<<<(nOut + 255) / 256, 256>>>(out, nOut);
    router_kernel<<<NTOK / 8, 256>>>(x, gw, gb);
    gemm1_kernel<<<dim3(F / BN, NTOK / BM, NE), 256>>>(x, w1, b1);
    gemm2_kernel<<<dim3(D / BN, NTOK / BM, NE), 256>>>(w2, b2, out);
    if (out_size > nOut) {
        aux_kernel<<<1, 1>>>(ema, out + nOut);
    }
}